// round 3
// baseline (speedup 1.0000x reference)
#include <cuda_runtime.h>
#include <math.h>

#define B  2
#define C  128
#define C4 32
#define T  512
#define Fd 256
#define EPS 1e-5f
#define QT 128
#define NEG -1.0e30f

// ---- scratch (static device memory; no allocation allowed) ----
__device__ float g_w12s[C * 64];      // fused+scaled w1|w2, layout [c][64]
__device__ float g_b12s[64];
__device__ float g_w3s[C4 * C];       // scaled w3, layout [c][128]
__device__ float g_b3s[C];
__device__ float g_x1[B * T * Fd * C4];   // [b][t][f][c]
__device__ float g_x2[B * Fd * T * C4];   // [b][f][t][c]
__device__ float g_of[B * Fd * T * C4];   // [b][f][t][c]
__device__ float g_M [B * Fd * T * C4];   // [b][f][t][c]

// ---------------------------------------------------------------------------
// Prep: fold BatchNorm into conv weights/biases.
// ---------------------------------------------------------------------------
__global__ void prep_kernel(const float* __restrict__ w1, const float* __restrict__ g1,
                            const float* __restrict__ b1, const float* __restrict__ m1,
                            const float* __restrict__ v1,
                            const float* __restrict__ w2, const float* __restrict__ g2,
                            const float* __restrict__ b2, const float* __restrict__ m2,
                            const float* __restrict__ v2,
                            const float* __restrict__ w3, const float* __restrict__ g3,
                            const float* __restrict__ b3, const float* __restrict__ m3,
                            const float* __restrict__ v3) {
    int total = C * 64 + C4 * C + 64 + C;
    for (int i = blockIdx.x * blockDim.x + threadIdx.x; i < total;
         i += gridDim.x * blockDim.x) {
        if (i < C * 64) {
            int c = i / 64, o = i % 64;
            float s, w;
            if (o < 32) { s = g1[o] * rsqrtf(v1[o] + EPS); w = w1[o * C + c]; }
            else        { int o2 = o - 32; s = g2[o2] * rsqrtf(v2[o2] + EPS); w = w2[o2 * C + c]; }
            g_w12s[c * 64 + o] = w * s;
        } else if (i < C * 64 + C4 * C) {
            int j = i - C * 64;
            int c = j / C, o = j % C;
            float s = g3[o] * rsqrtf(v3[o] + EPS);
            g_w3s[c * C + o] = w3[o * C4 + c] * s;
        } else if (i < C * 64 + C4 * C + 64) {
            int o = i - C * 64 - C4 * C;
            if (o < 32) { float s = g1[o] * rsqrtf(v1[o] + EPS); g_b12s[o] = b1[o] - m1[o] * s; }
            else        { int o2 = o - 32; float s = g2[o2] * rsqrtf(v2[o2] + EPS); g_b12s[o] = b2[o2] - m2[o2] * s; }
        } else {
            int o = i - C * 64 - C4 * C - 64;
            float s = g3[o] * rsqrtf(v3[o] + EPS);
            g_b3s[o] = b3[o] - m3[o] * s;
        }
    }
}

// ---------------------------------------------------------------------------
// Fused pointwise conv 1+2 (+BN +PReLU)
// ---------------------------------------------------------------------------
__global__ void conv12_kernel(const float* __restrict__ x,
                              const float* __restrict__ a1p,
                              const float* __restrict__ a2p) {
    __shared__ float sw[C * 64];
    __shared__ float sb[64];
    int tid = threadIdx.x;
    for (int i = tid; i < C * 64; i += 256) sw[i] = g_w12s[i];
    if (tid < 64) sb[tid] = g_b12s[tid];
    __syncthreads();

    int idx = blockIdx.x * 256 + tid;
    int f = idx % Fd;
    int t = (idx / Fd) % T;
    int b = idx / (Fd * T);

    float acc[64];
#pragma unroll
    for (int o = 0; o < 64; o++) acc[o] = sb[o];

    const float* xp = x + (b * C) * (T * Fd) + t * Fd + f;
#pragma unroll 2
    for (int c = 0; c < C; c++) {
        float xc = xp[c * (T * Fd)];
        const float4* wp = (const float4*)(&sw[c * 64]);
#pragma unroll
        for (int o4 = 0; o4 < 16; o4++) {
            float4 w = wp[o4];
            acc[o4 * 4 + 0] += xc * w.x;
            acc[o4 * 4 + 1] += xc * w.y;
            acc[o4 * 4 + 2] += xc * w.z;
            acc[o4 * 4 + 3] += xc * w.w;
        }
    }
    float a1 = a1p[0], a2 = a2p[0];

    float4* p1 = (float4*)(&g_x1[((b * T + t) * Fd + f) * C4]);
#pragma unroll
    for (int o4 = 0; o4 < 8; o4++) {
        float4 v; float y;
        y = acc[o4 * 4 + 0]; v.x = y >= 0.f ? y : a1 * y;
        y = acc[o4 * 4 + 1]; v.y = y >= 0.f ? y : a1 * y;
        y = acc[o4 * 4 + 2]; v.z = y >= 0.f ? y : a1 * y;
        y = acc[o4 * 4 + 3]; v.w = y >= 0.f ? y : a1 * y;
        p1[o4] = v;
    }
    float4* p2 = (float4*)(&g_x2[((b * Fd + f) * T + t) * C4]);
#pragma unroll
    for (int o4 = 0; o4 < 8; o4++) {
        float4 v; float y;
        y = acc[32 + o4 * 4 + 0]; v.x = y >= 0.f ? y : a2 * y;
        y = acc[32 + o4 * 4 + 1]; v.y = y >= 0.f ? y : a2 * y;
        y = acc[32 + o4 * 4 + 2]; v.z = y >= 0.f ? y : a2 * y;
        y = acc[32 + o4 * 4 + 3]; v.w = y >= 0.f ? y : a2 * y;
        p2[o4] = v;
    }
}

// ---------------------------------------------------------------------------
// Frequency attention (non-causal), chunked online softmax (chunk=8).
// One block per (b,t); thread f owns output row f. X tile [256,32] in SMEM.
// ---------------------------------------------------------------------------
__global__ void freq_attn_kernel() {
    __shared__ float X[Fd * C4];   // 32 KB
    int b = blockIdx.x / T;
    int t = blockIdx.x % T;
    int f = threadIdx.x;

    const float4* src = (const float4*)(&g_x1[((b * T + t) * Fd) * C4]);
    float4* X4 = (float4*)X;
#pragma unroll
    for (int i = 0; i < 8; i++) X4[f + i * Fd] = src[f + i * Fd];
    __syncthreads();

    float q[C4];
#pragma unroll
    for (int c = 0; c < C4; c++) q[c] = X[f * C4 + c];

    float mx = -3.0e38f, l = 0.f;
    float acc[C4];
#pragma unroll
    for (int c = 0; c < C4; c++) acc[c] = 0.f;

    const float inv = 1.0f / 128.0f;   // 1/sqrt(C*F/2)
    for (int s0 = 0; s0 < Fd; s0 += 8) {
        float sc8[8];
#pragma unroll
        for (int j = 0; j < 8; j++) {
            const float4* kp = (const float4*)(&X[(s0 + j) * C4]);
            float sv = 0.f;
#pragma unroll
            for (int c4 = 0; c4 < 8; c4++) {
                float4 k = kp[c4];
                sv += q[c4 * 4 + 0] * k.x + q[c4 * 4 + 1] * k.y
                    + q[c4 * 4 + 2] * k.z + q[c4 * 4 + 3] * k.w;
            }
            sc8[j] = sv * inv;
        }
        float cm = sc8[0];
#pragma unroll
        for (int j = 1; j < 8; j++) cm = fmaxf(cm, sc8[j]);
        float nm = fmaxf(mx, cm);
        float sc = __expf(mx - nm);
        l *= sc;
#pragma unroll
        for (int c = 0; c < C4; c++) acc[c] *= sc;
        mx = nm;
#pragma unroll
        for (int j = 0; j < 8; j++) {
            float p = __expf(sc8[j] - nm);
            l += p;
            const float4* vp = (const float4*)(&X[(s0 + j) * C4]);
#pragma unroll
            for (int c4 = 0; c4 < 8; c4++) {
                float4 v = vp[c4];
                acc[c4 * 4 + 0] += p * v.x;
                acc[c4 * 4 + 1] += p * v.y;
                acc[c4 * 4 + 2] += p * v.z;
                acc[c4 * 4 + 3] += p * v.w;
            }
        }
    }
    float rl = 1.f / l;
    float4* dst = (float4*)(&g_of[((b * Fd + f) * T + t) * C4]);
#pragma unroll
    for (int c4 = 0; c4 < 8; c4++) {
        float4 v;
        v.x = acc[c4 * 4 + 0] * rl; v.y = acc[c4 * 4 + 1] * rl;
        v.z = acc[c4 * 4 + 2] * rl; v.w = acc[c4 * 4 + 3] * rl;
        dst[c4] = v;
    }
}

// ---------------------------------------------------------------------------
// Causal time attention, chunked softmax + q-tile blocks for load balance.
// Block = (b*Fd+f, qtile); 128 threads; thread owns query row t=qt*128+tid.
// Iterates only s-tiles 0..qt. Smem tiles padded by 8 zero rows so the
// chunk loop can over-read past the causal boundary (masked scores -> p=0).
// ---------------------------------------------------------------------------
__global__ void time_attn_kernel() {
    __shared__ float Ks[(QT + 8) * C4];   // 17 KB
    __shared__ float Vs[(QT + 8) * C4];   // 17 KB
    int blk = blockIdx.x;
    int qt  = blk & 3;            // T/QT = 4 q-tiles
    int bf  = blk >> 2;           // b*Fd + f
    int tid = threadIdx.x;        // 0..127
    int t   = qt * QT + tid;
    int base = bf * (T * C4);

    // zero the pad rows once (never overwritten by tile loads)
    if (tid < 64) {
        ((float4*)(Ks + QT * C4))[tid] = make_float4(0.f, 0.f, 0.f, 0.f);
        ((float4*)(Vs + QT * C4))[tid] = make_float4(0.f, 0.f, 0.f, 0.f);
    }

    float q[C4];
    const float4* qs = (const float4*)(&g_x2[base + t * C4]);
#pragma unroll
    for (int c4 = 0; c4 < 8; c4++) {
        float4 v = qs[c4];
        q[c4 * 4 + 0] = v.x; q[c4 * 4 + 1] = v.y;
        q[c4 * 4 + 2] = v.z; q[c4 * 4 + 3] = v.w;
    }

    float mx = -3.0e38f, l = 0.f;
    float acc[C4];
#pragma unroll
    for (int c = 0; c < C4; c++) acc[c] = 0.f;

    const float inv = 0.005524271728019903f;  // 1/sqrt(C*T/2) = 2^-7.5

    for (int st = 0; st <= qt; st++) {
        __syncthreads();
        {
            const float4* ks = (const float4*)(&g_x2[base + st * QT * C4]);
            const float4* vs = (const float4*)(&g_of[base + st * QT * C4]);
            float4* K4 = (float4*)Ks;
            float4* V4 = (float4*)Vs;
#pragma unroll
            for (int i = 0; i < 8; i++) {
                K4[tid + i * 128] = ks[tid + i * 128];
                V4[tid + i * 128] = vs[tid + i * 128];
            }
        }
        __syncthreads();

        int send = (st < qt) ? QT : (tid + 1);   // exclusive count of valid rows
        for (int s0 = 0; s0 < send; s0 += 8) {
            float sc8[8];
#pragma unroll
            for (int j = 0; j < 8; j++) {
                int sl = s0 + j;                 // may exceed send; pad rows are zero
                const float4* kp = (const float4*)(&Ks[sl * C4]);
                float sv = 0.f;
#pragma unroll
                for (int c4 = 0; c4 < 8; c4++) {
                    float4 k = kp[c4];
                    sv += q[c4 * 4 + 0] * k.x + q[c4 * 4 + 1] * k.y
                        + q[c4 * 4 + 2] * k.z + q[c4 * 4 + 3] * k.w;
                }
                sc8[j] = (sl < send) ? sv * inv : NEG;
            }
            float cm = sc8[0];
#pragma unroll
            for (int j = 1; j < 8; j++) cm = fmaxf(cm, sc8[j]);
            float nm = fmaxf(mx, cm);
            float sc = __expf(mx - nm);
            l *= sc;
#pragma unroll
            for (int c = 0; c < C4; c++) acc[c] *= sc;
            mx = nm;
#pragma unroll
            for (int j = 0; j < 8; j++) {
                float p = __expf(sc8[j] - nm);
                l += p;
                const float4* vp = (const float4*)(&Vs[(s0 + j) * C4]);
#pragma unroll
                for (int c4 = 0; c4 < 8; c4++) {
                    float4 v = vp[c4];
                    acc[c4 * 4 + 0] += p * v.x;
                    acc[c4 * 4 + 1] += p * v.y;
                    acc[c4 * 4 + 2] += p * v.z;
                    acc[c4 * 4 + 3] += p * v.w;
                }
            }
        }
    }

    float rl = 1.f / l;
    float4* dst = (float4*)(&g_M[base + t * C4]);
#pragma unroll
    for (int c4 = 0; c4 < 8; c4++) {
        float4 v;
        v.x = acc[c4 * 4 + 0] * rl; v.y = acc[c4 * 4 + 1] * rl;
        v.z = acc[c4 * 4 + 2] * rl; v.w = acc[c4 * 4 + 3] * rl;
        dst[c4] = v;
    }
}

// ---------------------------------------------------------------------------
// Final pointwise conv (+BN +PReLU) + residual.
// ---------------------------------------------------------------------------
__global__ void final_kernel(const float* __restrict__ x,
                             const float* __restrict__ a3p,
                             float* __restrict__ out) {
    __shared__ float sw[C4 * C];
    __shared__ float sb[C];
    int tid = threadIdx.x;
    for (int i = tid; i < C4 * C; i += 256) sw[i] = g_w3s[i];
    if (tid < C) sb[tid] = g_b3s[tid];
    __syncthreads();

    int idx = blockIdx.x * 256 + tid;
    int f = idx % Fd;
    int t = (idx / Fd) % T;
    int b = idx / (Fd * T);

    float Ml[C4];
    const float4* ms = (const float4*)(&g_M[((b * Fd + f) * T + t) * C4]);
#pragma unroll
    for (int c4 = 0; c4 < 8; c4++) {
        float4 m = ms[c4];
        Ml[c4 * 4 + 0] = m.x; Ml[c4 * 4 + 1] = m.y;
        Ml[c4 * 4 + 2] = m.z; Ml[c4 * 4 + 3] = m.w;
    }
    float a3 = a3p[0];
    int xbase = (b * C) * (T * Fd) + t * Fd + f;
#pragma unroll 4
    for (int o = 0; o < C; o++) {
        float y = sb[o];
#pragma unroll
        for (int c = 0; c < C4; c++) y += Ml[c] * sw[c * C + o];
        y = y >= 0.f ? y : a3 * y;
        out[xbase + o * (T * Fd)] = y + x[xbase + o * (T * Fd)];
    }
}

// ---------------------------------------------------------------------------
extern "C" void kernel_launch(void* const* d_in, const int* in_sizes, int n_in,
                              void* d_out, int out_size) {
    const float* x  = (const float*)d_in[0];
    const float* w1 = (const float*)d_in[1];
    const float* g1 = (const float*)d_in[2];
    const float* b1 = (const float*)d_in[3];
    const float* m1 = (const float*)d_in[4];
    const float* v1 = (const float*)d_in[5];
    const float* a1 = (const float*)d_in[6];
    const float* w2 = (const float*)d_in[7];
    const float* g2 = (const float*)d_in[8];
    const float* b2 = (const float*)d_in[9];
    const float* m2 = (const float*)d_in[10];
    const float* v2 = (const float*)d_in[11];
    const float* a2 = (const float*)d_in[12];
    const float* w3 = (const float*)d_in[13];
    const float* g3 = (const float*)d_in[14];
    const float* b3 = (const float*)d_in[15];
    const float* m3 = (const float*)d_in[16];
    const float* v3 = (const float*)d_in[17];
    const float* a3 = (const float*)d_in[18];
    float* out = (float*)d_out;

    prep_kernel<<<16, 256>>>(w1, g1, b1, m1, v1, w2, g2, b2, m2, v2,
                             w3, g3, b3, m3, v3);
    conv12_kernel<<<(B * T * Fd) / 256, 256>>>(x, a1, a2);
    freq_attn_kernel<<<B * T, Fd>>>();
    time_attn_kernel<<<B * Fd * (T / QT), QT>>>();
    final_kernel<<<(B * T * Fd) / 256, 256>>>(x, a3, out);
}

// round 4
// speedup vs baseline: 1.3417x; 1.3417x over previous
#include <cuda_runtime.h>
#include <math.h>

#define B  2
#define C  128
#define C4 32
#define T  512
#define Fd 256
#define EPS 1e-5f
#define QT 128
#define NEG -1.0e30f

// ---- scratch (static device memory; no allocation allowed) ----
__device__ float g_w12s[C * 64];      // fused+scaled w1|w2, layout [c][64]
__device__ float g_b12s[64];
__device__ float g_w3s[C4 * C];       // scaled w3, layout [c][128]
__device__ float g_b3s[C];
__device__ float g_x1[B * T * Fd * C4];   // [b][t][f][c]
__device__ float g_x2[B * Fd * T * C4];   // [b][f][t][c]
__device__ float g_of[B * Fd * T * C4];   // [b][f][t][c]
__device__ float g_M [B * Fd * T * C4];   // [b][f][t][c]

// ---------------------------------------------------------------------------
// Prep: fold BatchNorm into conv weights/biases.
// ---------------------------------------------------------------------------
__global__ void prep_kernel(const float* __restrict__ w1, const float* __restrict__ g1,
                            const float* __restrict__ b1, const float* __restrict__ m1,
                            const float* __restrict__ v1,
                            const float* __restrict__ w2, const float* __restrict__ g2,
                            const float* __restrict__ b2, const float* __restrict__ m2,
                            const float* __restrict__ v2,
                            const float* __restrict__ w3, const float* __restrict__ g3,
                            const float* __restrict__ b3, const float* __restrict__ m3,
                            const float* __restrict__ v3) {
    int total = C * 64 + C4 * C + 64 + C;
    for (int i = blockIdx.x * blockDim.x + threadIdx.x; i < total;
         i += gridDim.x * blockDim.x) {
        if (i < C * 64) {
            int c = i / 64, o = i % 64;
            float s, w;
            if (o < 32) { s = g1[o] * rsqrtf(v1[o] + EPS); w = w1[o * C + c]; }
            else        { int o2 = o - 32; s = g2[o2] * rsqrtf(v2[o2] + EPS); w = w2[o2 * C + c]; }
            g_w12s[c * 64 + o] = w * s;
        } else if (i < C * 64 + C4 * C) {
            int j = i - C * 64;
            int c = j / C, o = j % C;
            float s = g3[o] * rsqrtf(v3[o] + EPS);
            g_w3s[c * C + o] = w3[o * C4 + c] * s;
        } else if (i < C * 64 + C4 * C + 64) {
            int o = i - C * 64 - C4 * C;
            if (o < 32) { float s = g1[o] * rsqrtf(v1[o] + EPS); g_b12s[o] = b1[o] - m1[o] * s; }
            else        { int o2 = o - 32; float s = g2[o2] * rsqrtf(v2[o2] + EPS); g_b12s[o] = b2[o2] - m2[o2] * s; }
        } else {
            int o = i - C * 64 - C4 * C - 64;
            float s = g3[o] * rsqrtf(v3[o] + EPS);
            g_b3s[o] = b3[o] - m3[o] * s;
        }
    }
}

// ---------------------------------------------------------------------------
// Fused pointwise conv 1+2 (+BN +PReLU)
// ---------------------------------------------------------------------------
__global__ void conv12_kernel(const float* __restrict__ x,
                              const float* __restrict__ a1p,
                              const float* __restrict__ a2p) {
    __shared__ float sw[C * 64];
    __shared__ float sb[64];
    int tid = threadIdx.x;
    for (int i = tid; i < C * 64; i += 256) sw[i] = g_w12s[i];
    if (tid < 64) sb[tid] = g_b12s[tid];
    __syncthreads();

    int idx = blockIdx.x * 256 + tid;
    int f = idx % Fd;
    int t = (idx / Fd) % T;
    int b = idx / (Fd * T);

    float acc[64];
#pragma unroll
    for (int o = 0; o < 64; o++) acc[o] = sb[o];

    const float* xp = x + (b * C) * (T * Fd) + t * Fd + f;
#pragma unroll 2
    for (int c = 0; c < C; c++) {
        float xc = xp[c * (T * Fd)];
        const float4* wp = (const float4*)(&sw[c * 64]);
#pragma unroll
        for (int o4 = 0; o4 < 16; o4++) {
            float4 w = wp[o4];
            acc[o4 * 4 + 0] += xc * w.x;
            acc[o4 * 4 + 1] += xc * w.y;
            acc[o4 * 4 + 2] += xc * w.z;
            acc[o4 * 4 + 3] += xc * w.w;
        }
    }
    float a1 = a1p[0], a2 = a2p[0];

    float4* p1 = (float4*)(&g_x1[((b * T + t) * Fd + f) * C4]);
#pragma unroll
    for (int o4 = 0; o4 < 8; o4++) {
        float4 v; float y;
        y = acc[o4 * 4 + 0]; v.x = y >= 0.f ? y : a1 * y;
        y = acc[o4 * 4 + 1]; v.y = y >= 0.f ? y : a1 * y;
        y = acc[o4 * 4 + 2]; v.z = y >= 0.f ? y : a1 * y;
        y = acc[o4 * 4 + 3]; v.w = y >= 0.f ? y : a1 * y;
        p1[o4] = v;
    }
    float4* p2 = (float4*)(&g_x2[((b * Fd + f) * T + t) * C4]);
#pragma unroll
    for (int o4 = 0; o4 < 8; o4++) {
        float4 v; float y;
        y = acc[32 + o4 * 4 + 0]; v.x = y >= 0.f ? y : a2 * y;
        y = acc[32 + o4 * 4 + 1]; v.y = y >= 0.f ? y : a2 * y;
        y = acc[32 + o4 * 4 + 2]; v.z = y >= 0.f ? y : a2 * y;
        y = acc[32 + o4 * 4 + 3]; v.w = y >= 0.f ? y : a2 * y;
        p2[o4] = v;
    }
}

// ---------------------------------------------------------------------------
// Frequency attention (non-causal), per-source online softmax (R2 form,
// minus the kg[32] unpack to lower register pressure).
// One block per (b,t); thread f owns output row f. X tile [256,32] in SMEM.
// ---------------------------------------------------------------------------
__global__ void freq_attn_kernel() {
    __shared__ float X[Fd * C4];   // 32 KB
    int b = blockIdx.x / T;
    int t = blockIdx.x % T;
    int f = threadIdx.x;

    const float4* src = (const float4*)(&g_x1[((b * T + t) * Fd) * C4]);
    float4* X4 = (float4*)X;
#pragma unroll
    for (int i = 0; i < 8; i++) X4[f + i * Fd] = src[f + i * Fd];
    __syncthreads();

    float q[C4];
#pragma unroll
    for (int c = 0; c < C4; c++) q[c] = X[f * C4 + c];

    float mx = -3.0e38f, l = 0.f;
    float acc[C4];
#pragma unroll
    for (int c = 0; c < C4; c++) acc[c] = 0.f;

    const float inv = 1.0f / 128.0f;   // 1/sqrt(C*F/2)
    for (int g = 0; g < Fd; g++) {
        const float4* kp = (const float4*)(&X[g * C4]);
        float s = 0.f;
#pragma unroll
        for (int c4 = 0; c4 < 8; c4++) {
            float4 k = kp[c4];
            s += q[c4 * 4 + 0] * k.x + q[c4 * 4 + 1] * k.y
               + q[c4 * 4 + 2] * k.z + q[c4 * 4 + 3] * k.w;
        }
        s *= inv;
        float nm = fmaxf(mx, s);
        float sc = __expf(mx - nm);
        float p  = __expf(s  - nm);
        l = l * sc + p;
#pragma unroll
        for (int c4 = 0; c4 < 8; c4++) {
            float4 k = kp[c4];
            acc[c4 * 4 + 0] = acc[c4 * 4 + 0] * sc + p * k.x;
            acc[c4 * 4 + 1] = acc[c4 * 4 + 1] * sc + p * k.y;
            acc[c4 * 4 + 2] = acc[c4 * 4 + 2] * sc + p * k.z;
            acc[c4 * 4 + 3] = acc[c4 * 4 + 3] * sc + p * k.w;
        }
        mx = nm;
    }
    float rl = 1.f / l;
    float4* dst = (float4*)(&g_of[((b * Fd + f) * T + t) * C4]);
#pragma unroll
    for (int c4 = 0; c4 < 8; c4++) {
        float4 v;
        v.x = acc[c4 * 4 + 0] * rl; v.y = acc[c4 * 4 + 1] * rl;
        v.z = acc[c4 * 4 + 2] * rl; v.w = acc[c4 * 4 + 3] * rl;
        dst[c4] = v;
    }
}

// ---------------------------------------------------------------------------
// Causal time attention, chunked softmax + q-tile blocks for load balance.
// Block = (b*Fd+f, qtile); 128 threads; thread owns query row t=qt*128+tid.
// ---------------------------------------------------------------------------
__global__ void time_attn_kernel() {
    __shared__ float Ks[(QT + 8) * C4];   // 17 KB
    __shared__ float Vs[(QT + 8) * C4];   // 17 KB
    int blk = blockIdx.x;
    int qt  = blk & 3;            // T/QT = 4 q-tiles
    int bf  = blk >> 2;           // b*Fd + f
    int tid = threadIdx.x;        // 0..127
    int t   = qt * QT + tid;
    int base = bf * (T * C4);

    if (tid < 64) {
        ((float4*)(Ks + QT * C4))[tid] = make_float4(0.f, 0.f, 0.f, 0.f);
        ((float4*)(Vs + QT * C4))[tid] = make_float4(0.f, 0.f, 0.f, 0.f);
    }

    float q[C4];
    const float4* qs = (const float4*)(&g_x2[base + t * C4]);
#pragma unroll
    for (int c4 = 0; c4 < 8; c4++) {
        float4 v = qs[c4];
        q[c4 * 4 + 0] = v.x; q[c4 * 4 + 1] = v.y;
        q[c4 * 4 + 2] = v.z; q[c4 * 4 + 3] = v.w;
    }

    float mx = -3.0e38f, l = 0.f;
    float acc[C4];
#pragma unroll
    for (int c = 0; c < C4; c++) acc[c] = 0.f;

    const float inv = 0.005524271728019903f;  // 1/sqrt(C*T/2) = 2^-7.5

    for (int st = 0; st <= qt; st++) {
        __syncthreads();
        {
            const float4* ks = (const float4*)(&g_x2[base + st * QT * C4]);
            const float4* vs = (const float4*)(&g_of[base + st * QT * C4]);
            float4* K4 = (float4*)Ks;
            float4* V4 = (float4*)Vs;
#pragma unroll
            for (int i = 0; i < 8; i++) {
                K4[tid + i * 128] = ks[tid + i * 128];
                V4[tid + i * 128] = vs[tid + i * 128];
            }
        }
        __syncthreads();

        int send = (st < qt) ? QT : (tid + 1);   // exclusive count of valid rows
        for (int s0 = 0; s0 < send; s0 += 8) {
            float sc8[8];
#pragma unroll
            for (int j = 0; j < 8; j++) {
                int sl = s0 + j;                 // may exceed send; pad rows are zero
                const float4* kp = (const float4*)(&Ks[sl * C4]);
                float sv = 0.f;
#pragma unroll
                for (int c4 = 0; c4 < 8; c4++) {
                    float4 k = kp[c4];
                    sv += q[c4 * 4 + 0] * k.x + q[c4 * 4 + 1] * k.y
                        + q[c4 * 4 + 2] * k.z + q[c4 * 4 + 3] * k.w;
                }
                sc8[j] = (sl < send) ? sv * inv : NEG;
            }
            float cm = sc8[0];
#pragma unroll
            for (int j = 1; j < 8; j++) cm = fmaxf(cm, sc8[j]);
            float nm = fmaxf(mx, cm);
            float sc = __expf(mx - nm);
            l *= sc;
#pragma unroll
            for (int c = 0; c < C4; c++) acc[c] *= sc;
            mx = nm;
#pragma unroll
            for (int j = 0; j < 8; j++) {
                float p = __expf(sc8[j] - nm);
                l += p;
                const float4* vp = (const float4*)(&Vs[(s0 + j) * C4]);
#pragma unroll
                for (int c4 = 0; c4 < 8; c4++) {
                    float4 v = vp[c4];
                    acc[c4 * 4 + 0] += p * v.x;
                    acc[c4 * 4 + 1] += p * v.y;
                    acc[c4 * 4 + 2] += p * v.z;
                    acc[c4 * 4 + 3] += p * v.w;
                }
            }
        }
    }

    float rl = 1.f / l;
    float4* dst = (float4*)(&g_M[base + t * C4]);
#pragma unroll
    for (int c4 = 0; c4 < 8; c4++) {
        float4 v;
        v.x = acc[c4 * 4 + 0] * rl; v.y = acc[c4 * 4 + 1] * rl;
        v.z = acc[c4 * 4 + 2] * rl; v.w = acc[c4 * 4 + 3] * rl;
        dst[c4] = v;
    }
}

// ---------------------------------------------------------------------------
// Final pointwise conv (+BN +PReLU) + residual. float4-vectorized over o.
// ---------------------------------------------------------------------------
__global__ void final_kernel(const float* __restrict__ x,
                             const float* __restrict__ a3p,
                             float* __restrict__ out) {
    __shared__ float sw[C4 * C];   // layout [c][128]
    __shared__ float sb[C];
    int tid = threadIdx.x;
    for (int i = tid; i < C4 * C; i += 256) sw[i] = g_w3s[i];
    if (tid < C) sb[tid] = g_b3s[tid];
    __syncthreads();

    int idx = blockIdx.x * 256 + tid;
    int f = idx % Fd;
    int t = (idx / Fd) % T;
    int b = idx / (Fd * T);

    float Ml[C4];
    const float4* ms = (const float4*)(&g_M[((b * Fd + f) * T + t) * C4]);
#pragma unroll
    for (int c4 = 0; c4 < 8; c4++) {
        float4 m = ms[c4];
        Ml[c4 * 4 + 0] = m.x; Ml[c4 * 4 + 1] = m.y;
        Ml[c4 * 4 + 2] = m.z; Ml[c4 * 4 + 3] = m.w;
    }
    float a3 = a3p[0];
    int xbase = (b * C) * (T * Fd) + t * Fd + f;
    const float4* sw4 = (const float4*)sw;     // [c][32] float4 rows
    const float4* sb4 = (const float4*)sb;
#pragma unroll 2
    for (int o4 = 0; o4 < C / 4; o4++) {
        float4 bb = sb4[o4];
        float y0 = bb.x, y1 = bb.y, y2 = bb.z, y3 = bb.w;
#pragma unroll
        for (int c = 0; c < C4; c++) {
            float4 w = sw4[c * (C / 4) + o4];
            float m = Ml[c];
            y0 += m * w.x; y1 += m * w.y; y2 += m * w.z; y3 += m * w.w;
        }
        y0 = y0 >= 0.f ? y0 : a3 * y0;
        y1 = y1 >= 0.f ? y1 : a3 * y1;
        y2 = y2 >= 0.f ? y2 : a3 * y2;
        y3 = y3 >= 0.f ? y3 : a3 * y3;
        int o = o4 * 4;
        out[xbase + (o + 0) * (T * Fd)] = y0 + x[xbase + (o + 0) * (T * Fd)];
        out[xbase + (o + 1) * (T * Fd)] = y1 + x[xbase + (o + 1) * (T * Fd)];
        out[xbase + (o + 2) * (T * Fd)] = y2 + x[xbase + (o + 2) * (T * Fd)];
        out[xbase + (o + 3) * (T * Fd)] = y3 + x[xbase + (o + 3) * (T * Fd)];
    }
}

// ---------------------------------------------------------------------------
extern "C" void kernel_launch(void* const* d_in, const int* in_sizes, int n_in,
                              void* d_out, int out_size) {
    const float* x  = (const float*)d_in[0];
    const float* w1 = (const float*)d_in[1];
    const float* g1 = (const float*)d_in[2];
    const float* b1 = (const float*)d_in[3];
    const float* m1 = (const float*)d_in[4];
    const float* v1 = (const float*)d_in[5];
    const float* a1 = (const float*)d_in[6];
    const float* w2 = (const float*)d_in[7];
    const float* g2 = (const float*)d_in[8];
    const float* b2 = (const float*)d_in[9];
    const float* m2 = (const float*)d_in[10];
    const float* v2 = (const float*)d_in[11];
    const float* a2 = (const float*)d_in[12];
    const float* w3 = (const float*)d_in[13];
    const float* g3 = (const float*)d_in[14];
    const float* b3 = (const float*)d_in[15];
    const float* m3 = (const float*)d_in[16];
    const float* v3 = (const float*)d_in[17];
    const float* a3 = (const float*)d_in[18];
    float* out = (float*)d_out;

    prep_kernel<<<16, 256>>>(w1, g1, b1, m1, v1, w2, g2, b2, m2, v2,
                             w3, g3, b3, m3, v3);
    conv12_kernel<<<(B * T * Fd) / 256, 256>>>(x, a1, a2);
    freq_attn_kernel<<<B * T, Fd>>>();
    time_attn_kernel<<<B * Fd * (T / QT), QT>>>();
    final_kernel<<<(B * T * Fd) / 256, 256>>>(x, a3, out);
}